// round 9
// baseline (speedup 1.0000x reference)
#include <cuda_runtime.h>
#include <cuda_bf16.h>
#include <cstddef>

#define NN 50000
#define NE 800000
#define C0 128   // in channels
#define C1 256   // hidden
#define C2 64    // latent

// ---------------- scratch (device globals; no allocation allowed) ----------------
__device__ int   g_deg[NN];
__device__ float g_dinv[NN];
__device__ int   g_is64;
__device__ int   g_src[NE];
__device__ int   g_dst[NE];
__device__ float g_aggx[(size_t)NN * C0];  // A @ x            (25.6 MB)
__device__ float g_h1  [(size_t)NN * C1];  // relu(aggx@W1+b1) (51.2 MB)
__device__ float g_t2  [(size_t)NN * C2];  // h1 @ W2          (12.8 MB)
__device__ float g_z   [(size_t)NN * C2];  // A @ t2 + b2      (12.8 MB)
__device__ float g_dd  [(size_t)NN * C1];  // relu(z@Wd1+bd1)  (51.2 MB)

// ---------------- helpers ----------------
__device__ __forceinline__ void red_add_v4(float* addr, float4 v) {
    asm volatile("red.global.add.v4.f32 [%0], {%1,%2,%3,%4};"
                 :: "l"(addr), "f"(v.x), "f"(v.y), "f"(v.z), "f"(v.w)
                 : "memory");
}

// ---------------- small kernels ----------------
// Zero degree array; thread 0 also detects whether edge_index elements are
// 8 bytes (int64) or 4 bytes (int32). If the buffer is int32, an int64 read
// packs two random node ids; the high word is nonzero with overwhelming
// probability, so 64 probes make a false-positive astronomically unlikely.
// The kernel boundary before k_decode_count orders g_is64 for all readers.
__global__ void k_prep(const void* ei) {
    int i = blockIdx.x * blockDim.x + threadIdx.x;
    if (i < NN) g_deg[i] = 0;
    if (i == 0) {
        const long long* p = (const long long*)ei;
        int ok = 1;
        for (int q = 0; q < 64; q++) {
            long long v = p[q];
            if (v < 0 || v >= NN) { ok = 0; break; }
        }
        g_is64 = ok;
    }
}

// decode indices once into int32 pairs + count in-degree; 4 edges per thread
// (NE % 4 == 0, so no tail handling needed)
__global__ void k_decode_count(const void* ei) {
    int t = blockIdx.x * blockDim.x + threadIdx.x;
    if (t >= NE / 4) return;
    int e = t * 4;
    int4 s4, d4;
    if (g_is64) {
        const longlong2* ps = (const longlong2*)((const long long*)ei + e);
        const longlong2* pd = (const longlong2*)((const long long*)ei + NE + e);
        longlong2 s01 = ps[0], s23 = ps[1];
        longlong2 d01 = pd[0], d23 = pd[1];
        s4 = make_int4((int)s01.x, (int)s01.y, (int)s23.x, (int)s23.y);
        d4 = make_int4((int)d01.x, (int)d01.y, (int)d23.x, (int)d23.y);
    } else {
        s4 = *(const int4*)((const int*)ei + e);
        d4 = *(const int4*)((const int*)ei + NE + e);
    }
    *(int4*)(g_src + e) = s4;
    *(int4*)(g_dst + e) = d4;
    atomicAdd(&g_deg[d4.x], 1);
    atomicAdd(&g_deg[d4.y], 1);
    atomicAdd(&g_deg[d4.z], 1);
    atomicAdd(&g_deg[d4.w], 1);
}

__global__ void k_dinv() {
    int i = blockIdx.x * blockDim.x + threadIdx.x;
    if (i < NN) g_dinv[i] = rsqrtf((float)g_deg[i] + 1.0f);  // +1 self loop
}

// aggx[i] = dinv[i]^2 * x[i]   (self-loop message), vectorized float4
__global__ void k_init_aggx(const float* __restrict__ x) {
    int t = blockIdx.x * blockDim.x + threadIdx.x;   // over NN*32 float4s
    if (t >= NN * (C0 / 4)) return;
    int node = t / (C0 / 4);
    float s = g_dinv[node]; s *= s;
    float4 v = ((const float4*)x)[t];
    v.x *= s; v.y *= s; v.z *= s; v.w *= s;
    ((float4*)g_aggx)[t] = v;
}

// aggx[dst] += dinv[s]*dinv[d] * x[src] — one warp per edge (32 float4 lanes)
__global__ void k_scatter1(const float* __restrict__ x) {
    int gt = blockIdx.x * blockDim.x + threadIdx.x;
    int e = gt >> 5;
    int lane = gt & 31;
    if (e >= NE) return;
    int s = g_src[e], d = g_dst[e];
    float norm = g_dinv[s] * g_dinv[d];   // broadcast loads, L1-resident
    float4 v = ((const float4*)x)[(size_t)s * (C0 / 4) + lane];
    v.x *= norm; v.y *= norm; v.z *= norm; v.w *= norm;
    red_add_v4(g_aggx + (size_t)d * C0 + lane * 4, v);
}

// z[dst] += dinv[s]*dinv[d] * t2[src] — 16 lanes per edge (64 ch)
__global__ void k_scatter2() {
    int gt = blockIdx.x * blockDim.x + threadIdx.x;
    int e = gt >> 4;
    int lane = gt & 15;
    if (e >= NE) return;
    int s = g_src[e], d = g_dst[e];
    float norm = g_dinv[s] * g_dinv[d];
    float4 v = ((const float4*)g_t2)[(size_t)s * (C2 / 4) + lane];
    v.x *= norm; v.y *= norm; v.z *= norm; v.w *= norm;
    red_add_v4(g_z + (size_t)d * C2 + lane * 4, v);
}

// ---------------- GEMM: C[M,N] = A[M,K] @ B[K,N] (+bias) (+relu) ----------------
// Block tile 128 x BN, 256 threads, thread tile 8 x (BN/16), BK=16.
// Compile-time K; double-buffered smem; register prefetch; LDS.128 fragments;
// vectorized STG.128 epilogue.
// ZOUT: additionally emit Z[m,n] = dinv[m]^2 * C[m,n] + zbias[n] (self-loop
// init for the following scatter pass), folding away a separate init kernel.
template <int BN, int K, int RELU, int BIAS, int ZOUT>
__global__ __launch_bounds__(256)
void k_gemm(const float* __restrict__ A, const float* __restrict__ B,
            const float* __restrict__ bias, float* __restrict__ C,
            int M, int Nn,
            float* __restrict__ Z = nullptr,
            const float* __restrict__ zbias = nullptr) {
    constexpr int TN = BN / 16;          // 8 (BN=128) or 4 (BN=64)
    constexpr int NB = BN / 64;          // B float4 loads per thread
    constexpr int nT = K / 16;
    __shared__ float As[2][16][128];
    __shared__ float Bs[2][16][BN];
    int tid = threadIdx.x;
    int m0 = blockIdx.x * 128, n0 = blockIdx.y * BN;
    int ty = tid >> 4, tx = tid & 15;    // 16 x 16 thread grid

    // staging-load index precompute
    int af0 = tid * 2;                   // A: threads cover 512 float4s (128x16)
    int ar[2], akc[2];
#pragma unroll
    for (int q = 0; q < 2; q++) { ar[q] = (af0 + q) >> 2; akc[q] = ((af0 + q) & 3) << 2; }
    int br[NB], bnc[NB];
#pragma unroll
    for (int q = 0; q < NB; q++) {
        int f = tid + q * 256;
        br[q] = f / (BN / 4); bnc[q] = (f % (BN / 4)) * 4;
    }

    float acc[8][TN];
#pragma unroll
    for (int i = 0; i < 8; i++)
#pragma unroll
        for (int j = 0; j < TN; j++) acc[i][j] = 0.f;

    float4 ra[2], rb[NB];

    // prologue: fetch tile 0
#pragma unroll
    for (int q = 0; q < 2; q++)
        ra[q] = (m0 + ar[q] < M)
            ? *(const float4*)(A + (size_t)(m0 + ar[q]) * K + akc[q])
            : make_float4(0.f, 0.f, 0.f, 0.f);
#pragma unroll
    for (int q = 0; q < NB; q++)
        rb[q] = *(const float4*)(B + (size_t)br[q] * Nn + n0 + bnc[q]);
#pragma unroll
    for (int q = 0; q < 2; q++) {
        As[0][akc[q] + 0][ar[q]] = ra[q].x; As[0][akc[q] + 1][ar[q]] = ra[q].y;
        As[0][akc[q] + 2][ar[q]] = ra[q].z; As[0][akc[q] + 3][ar[q]] = ra[q].w;
    }
#pragma unroll
    for (int q = 0; q < NB; q++)
        *(float4*)&Bs[0][br[q]][bnc[q]] = rb[q];
    __syncthreads();

    int buf = 0;
#pragma unroll 1
    for (int t = 0; t < nT; t++) {
        // prefetch next tile into registers
        if (t + 1 < nT) {
            int k0n = (t + 1) * 16;
#pragma unroll
            for (int q = 0; q < 2; q++)
                ra[q] = (m0 + ar[q] < M)
                    ? *(const float4*)(A + (size_t)(m0 + ar[q]) * K + k0n + akc[q])
                    : make_float4(0.f, 0.f, 0.f, 0.f);
#pragma unroll
            for (int q = 0; q < NB; q++)
                rb[q] = *(const float4*)(B + (size_t)(k0n + br[q]) * Nn + n0 + bnc[q]);
        }
        // compute on current buffer — vectorized LDS.128 fragment loads
#pragma unroll
        for (int k = 0; k < 16; k++) {
            float a[8], b[TN];
            *(float4*)&a[0] = *(const float4*)&As[buf][k][ty * 4];
            *(float4*)&a[4] = *(const float4*)&As[buf][k][ty * 4 + 64];
            *(float4*)&b[0] = *(const float4*)&Bs[buf][k][tx * 4];
            if (TN == 8)
                *(float4*)&b[4] = *(const float4*)&Bs[buf][k][tx * 4 + BN / 2];
#pragma unroll
            for (int i = 0; i < 8; i++)
#pragma unroll
                for (int j = 0; j < TN; j++)
                    acc[i][j] = fmaf(a[i], b[j], acc[i][j]);
        }
        // drain registers into the other buffer
        if (t + 1 < nT) {
            int nb = buf ^ 1;
#pragma unroll
            for (int q = 0; q < 2; q++) {
                As[nb][akc[q] + 0][ar[q]] = ra[q].x; As[nb][akc[q] + 1][ar[q]] = ra[q].y;
                As[nb][akc[q] + 2][ar[q]] = ra[q].z; As[nb][akc[q] + 3][ar[q]] = ra[q].w;
            }
#pragma unroll
            for (int q = 0; q < NB; q++)
                *(float4*)&Bs[nb][br[q]][bnc[q]] = rb[q];
            __syncthreads();
            buf = nb;
        }
    }

    // epilogue: acc[i][j] -> row ty*4 + (i>>2)*64 + (i&3),
    //                        col tx*4 + (j>>2)*(BN/2) + (j&3).
    // For fixed (j>>2), the 4 (j&3) columns are consecutive -> float4 stores.
    float4 bv[TN / 4], zbv[TN / 4];
#pragma unroll
    for (int g = 0; g < TN / 4; g++) {
        bv[g] = BIAS ? *(const float4*)(bias + n0 + tx * 4 + g * (BN / 2))
                     : make_float4(0.f, 0.f, 0.f, 0.f);
        if (ZOUT)
            zbv[g] = *(const float4*)(zbias + n0 + tx * 4 + g * (BN / 2));
    }
#pragma unroll
    for (int i = 0; i < 8; i++) {
        int m = m0 + ty * 4 + (i >> 2) * 64 + (i & 3);
        if (m >= M) continue;
        float s2 = 0.f;
        if (ZOUT) { float dv = g_dinv[m]; s2 = dv * dv; }
#pragma unroll
        for (int g = 0; g < TN / 4; g++) {
            float4 v;
            v.x = acc[i][g * 4 + 0] + bv[g].x;
            v.y = acc[i][g * 4 + 1] + bv[g].y;
            v.z = acc[i][g * 4 + 2] + bv[g].z;
            v.w = acc[i][g * 4 + 3] + bv[g].w;
            if (RELU) {
                v.x = fmaxf(v.x, 0.f); v.y = fmaxf(v.y, 0.f);
                v.z = fmaxf(v.z, 0.f); v.w = fmaxf(v.w, 0.f);
            }
            *(float4*)(C + (size_t)m * Nn + n0 + tx * 4 + g * (BN / 2)) = v;
            if (ZOUT) {
                float4 zv;
                zv.x = v.x * s2 + zbv[g].x;
                zv.y = v.y * s2 + zbv[g].y;
                zv.z = v.z * s2 + zbv[g].z;
                zv.w = v.w * s2 + zbv[g].w;
                *(float4*)(Z + (size_t)m * Nn + n0 + tx * 4 + g * (BN / 2)) = zv;
            }
        }
    }
}

// ---------------- launcher ----------------
extern "C" void kernel_launch(void* const* d_in, const int* in_sizes, int n_in,
                              void* d_out, int out_size) {
    const float* x   = (const float*)d_in[0];
    const void*  ei  = d_in[1];
    const float* W1  = (const float*)d_in[2];
    const float* b1  = (const float*)d_in[3];
    const float* W2  = (const float*)d_in[4];
    const float* b2  = (const float*)d_in[5];
    const float* Wd1 = (const float*)d_in[6];
    const float* bd1 = (const float*)d_in[7];
    const float* Wd2 = (const float*)d_in[8];
    const float* bd2 = (const float*)d_in[9];
    float* out = (float*)d_out;

    float *p_aggx, *p_h1, *p_t2, *p_z, *p_dd;
    cudaGetSymbolAddress((void**)&p_aggx, g_aggx);
    cudaGetSymbolAddress((void**)&p_h1,  g_h1);
    cudaGetSymbolAddress((void**)&p_t2,  g_t2);
    cudaGetSymbolAddress((void**)&p_z,   g_z);
    cudaGetSymbolAddress((void**)&p_dd,  g_dd);

    const int T = 256;
    // prep: zero degrees + dtype probe, decode + count, normalization
    k_prep<<<(NN + T - 1) / T, T>>>(ei);
    k_decode_count<<<(NE / 4 + T - 1) / T, T>>>(ei);
    k_dinv<<<(NN + T - 1) / T, T>>>();

    // layer 1: aggregate-then-transform  (A@x then @W1)
    k_init_aggx<<<(NN * (C0 / 4) + T - 1) / T, T>>>(x);
    k_scatter1<<<(NE * 32 + T - 1) / T, T>>>(x);
    k_gemm<128, C0, 1, 1, 0><<<dim3((NN + 127) / 128, C1 / 128), T>>>(
        p_aggx, W1, b1, p_h1, NN, C1);

    // layer 2: transform-then-aggregate (h1@W2 then A@); the GEMM epilogue
    // also emits z = dinv^2 * t2 + b2 (self-loop init), so no separate pass.
    k_gemm<64, C1, 0, 0, 1><<<dim3((NN + 127) / 128, 1), T>>>(
        p_h1, W2, nullptr, p_t2, NN, C2, p_z, b2);
    k_scatter2<<<(NE * 16 + T - 1) / T, T>>>();

    // decoder MLP
    k_gemm<128, C2, 1, 1, 0><<<dim3((NN + 127) / 128, C1 / 128), T>>>(
        p_z, Wd1, bd1, p_dd, NN, C1);
    k_gemm<128, C1, 0, 1, 0><<<dim3((NN + 127) / 128, C0 / 128), T>>>(
        p_dd, Wd2, bd2, out, NN, C0);
}